// round 12
// baseline (speedup 1.0000x reference)
#include <cuda_runtime.h>
#include <math.h>

#define NN 20000
#define EE 320000
#define LD 128
#define MAXIT 10

// ---------------- device scratch ----------------
__device__ __align__(16) float g_h[NN * LD];          // hidden state
__device__ __align__(16) float g_ab[NN * 2 * LD];     // [a | b] per node
__device__ __align__(16) float g_agg[NN * LD];        // aggregated messages
__device__ __align__(16) float g_pre[2ull * NN * 2 * LD]; // z_r @ [W1_top|W2_top], r in {0,1}
__device__ __align__(16) float g_u[NN];
__device__ __align__(16) float g_v[NN];
__device__ __align__(16) float g_alpha[EE];
__device__ int g_mx[NN];                              // max alpha bits over incident edges
__device__ unsigned long long g_pack[NN];             // (alpha_bits<<32)|(EE-1-e) max
__device__ int g_deg[NN];
__device__ int g_off[NN];
__device__ int g_cursor[NN];
__device__ int g_csrc[EE];                            // CSR-by-dst source ids

// ---------------- init ----------------
__global__ void init_kernel(const float* __restrict__ s) {
    int idx = blockIdx.x * blockDim.x + threadIdx.x;
    if (idx < NN * LD) g_h[idx] = 0.f;
    if (idx < NN) {
        g_deg[idx] = 0;
        g_mx[idx] = (s[idx] > 0.f) ? 0x3f800000 : 0;  // reach(iter0) = s
        g_pack[idx] = 0ull;
    }
}

// ---------------- CSR build (by dst) ----------------
__global__ void deg_kernel(const int* __restrict__ dst) {
    int e = blockIdx.x * blockDim.x + threadIdx.x;
    if (e < EE) atomicAdd(&g_deg[dst[e]], 1);
}

__global__ void scan_kernel() {  // single block, 1024 threads
    __shared__ int part[1024];
    int t = threadIdx.x;
    const int chunk = (NN + 1023) / 1024;
    int b0 = t * chunk;
    int acc = 0;
    for (int i = 0; i < chunk; i++) {
        int idx = b0 + i;
        if (idx < NN) acc += g_deg[idx];
    }
    part[t] = acc;
    __syncthreads();
    for (int o = 1; o < 1024; o <<= 1) {
        int v = (t >= o) ? part[t - o] : 0;
        __syncthreads();
        part[t] += v;
        __syncthreads();
    }
    int run = (t == 0) ? 0 : part[t - 1];
    for (int i = 0; i < chunk; i++) {
        int idx = b0 + i;
        if (idx < NN) {
            g_off[idx] = run;
            g_cursor[idx] = run;
            run += g_deg[idx];
        }
    }
}

__global__ void fill_kernel(const int* __restrict__ src, const int* __restrict__ dst) {
    int e = blockIdx.x * blockDim.x + threadIdx.x;
    if (e < EE) {
        int p = atomicAdd(&g_cursor[dst[e]], 1);
        g_csrc[p] = src[e];
    }
}

// ---------------- unified scalar-FFMA GEMM, BM=128 BN=128 BK=16, 8x8 microtile ----------------
// MODE 0: pre[r] = z_r(pos) @ [W1_top|W2_top]    grid (157,2,2)
// MODE 1: ab = h @ [W1_bot|W2_bot] + pre[reach]  grid (157,2)
// MODE 2: h = relu(agg @ Wout + bout)            grid (157,1)
template <int MODE>
__global__ __launch_bounds__(256, 2) void gemm_kernel(
    const float* __restrict__ B1, const float* __restrict__ B2,
    const float* __restrict__ pos, const float* __restrict__ We,
    const float* __restrict__ be, const float* __restrict__ bias) {
    __shared__ float As[16][132];
    __shared__ float Bs[16][128];
    int m0 = blockIdx.x * 128;
    int j0 = blockIdx.y * 128;
    int r = (MODE == 0) ? (int)blockIdx.z : 0;
    const float* Bptr = (MODE != 2 && j0 >= 128) ? B2 : B1;
    int t = threadIdx.x, tx = t & 15, ty = t >> 4;
    float c[8][8] = {};

    for (int kt = 0; kt < 128; kt += 16) {
        // A tile: 2048 floats = 512 float4, 2 per thread
#pragma unroll
        for (int rr = 0; rr < 2; rr++) {
            int f = t + rr * 256;
            int mloc = f >> 2, k4 = (f & 3) * 4;
            int m = m0 + mloc;
            float4 av = make_float4(0.f, 0.f, 0.f, 0.f);
            if (m < NN) {
                if (MODE == 0) {
                    float p = pos[m];
                    float rf = (float)r;
                    float4 w0 = *(const float4*)(We + kt + k4);
                    float4 w1 = *(const float4*)(We + 128 + kt + k4);
                    float4 b0 = *(const float4*)(be + kt + k4);
                    av.x = fmaxf(fmaf(p, w0.x, fmaf(rf, w1.x, b0.x)), 0.f);
                    av.y = fmaxf(fmaf(p, w0.y, fmaf(rf, w1.y, b0.y)), 0.f);
                    av.z = fmaxf(fmaf(p, w0.z, fmaf(rf, w1.z, b0.z)), 0.f);
                    av.w = fmaxf(fmaf(p, w0.w, fmaf(rf, w1.w, b0.w)), 0.f);
                } else if (MODE == 1) {
                    av = *(const float4*)(g_h + (size_t)m * 128 + kt + k4);
                } else {
                    av = *(const float4*)(g_agg + (size_t)m * 128 + kt + k4);
                }
            }
            As[k4 + 0][mloc] = av.x;
            As[k4 + 1][mloc] = av.y;
            As[k4 + 2][mloc] = av.z;
            As[k4 + 3][mloc] = av.w;
        }
        // B tile: 16x128 = 512 float4, 2 per thread
#pragma unroll
        for (int rr = 0; rr < 2; rr++) {
            int f = t + rr * 256;
            int kk = f >> 5, j4 = (f & 31) * 4;
            *(float4*)&Bs[kk][j4] = *(const float4*)(Bptr + (size_t)(kt + kk) * 128 + j4);
        }
        __syncthreads();
#pragma unroll
        for (int k = 0; k < 16; k++) {
            float4 a0 = *(const float4*)&As[k][ty * 8];
            float4 a1 = *(const float4*)&As[k][ty * 8 + 4];
            float4 b0 = *(const float4*)&Bs[k][tx * 8];
            float4 b1 = *(const float4*)&Bs[k][tx * 8 + 4];
            float ar[8] = {a0.x, a0.y, a0.z, a0.w, a1.x, a1.y, a1.z, a1.w};
            float br[8] = {b0.x, b0.y, b0.z, b0.w, b1.x, b1.y, b1.z, b1.w};
#pragma unroll
            for (int i = 0; i < 8; i++)
#pragma unroll
                for (int jj = 0; jj < 8; jj++) c[i][jj] = fmaf(ar[i], br[jj], c[i][jj]);
        }
        __syncthreads();
    }

    int jc = j0 + tx * 8;
#pragma unroll
    for (int i = 0; i < 8; i++) {
        int m = m0 + ty * 8 + i;
        if (m >= NN) continue;
        float4 v0 = make_float4(c[i][0], c[i][1], c[i][2], c[i][3]);
        float4 v1 = make_float4(c[i][4], c[i][5], c[i][6], c[i][7]);
        if (MODE == 0) {
            *(float4*)(g_pre + ((size_t)r * NN + m) * 256 + jc) = v0;
            *(float4*)(g_pre + ((size_t)r * NN + m) * 256 + jc + 4) = v1;
        } else if (MODE == 1) {
            int sel = (__int_as_float(g_mx[m]) >= 0.4f) ? 1 : 0;
            float4 p0 = *(const float4*)(g_pre + ((size_t)sel * NN + m) * 256 + jc);
            float4 p1 = *(const float4*)(g_pre + ((size_t)sel * NN + m) * 256 + jc + 4);
            v0.x += p0.x; v0.y += p0.y; v0.z += p0.z; v0.w += p0.w;
            v1.x += p1.x; v1.y += p1.y; v1.z += p1.z; v1.w += p1.w;
            *(float4*)(g_ab + (size_t)m * 256 + jc) = v0;
            *(float4*)(g_ab + (size_t)m * 256 + jc + 4) = v1;
        } else {
            float4 b0 = *(const float4*)(bias + jc);
            float4 b1 = *(const float4*)(bias + jc + 4);
            v0.x = fmaxf(v0.x + b0.x, 0.f);
            v0.y = fmaxf(v0.y + b0.y, 0.f);
            v0.z = fmaxf(v0.z + b0.z, 0.f);
            v0.w = fmaxf(v0.w + b0.w, 0.f);
            v1.x = fmaxf(v1.x + b1.x, 0.f);
            v1.y = fmaxf(v1.y + b1.y, 0.f);
            v1.z = fmaxf(v1.z + b1.z, 0.f);
            v1.w = fmaxf(v1.w + b1.w, 0.f);
            *(float4*)(g_h + (size_t)m * 128 + jc) = v0;
            *(float4*)(g_h + (size_t)m * 128 + jc + 4) = v1;
        }
    }
}

// ---------------- aggregate: agg[n] = relu(max_in a[src] + b[n] + bmsg) ----------------
// 2 nodes per block (256 threads), unroll-4 gather for MLP
__global__ __launch_bounds__(256) void aggregate_kernel(const float* __restrict__ bmsg) {
    int n = blockIdx.x * 2 + (threadIdx.x >> 7);
    int l = threadIdx.x & 127;
    if (n >= NN) return;
    int beg = g_off[n];
    int d = g_deg[n];
    float out = 0.f;
    if (d > 0) {
        const int* cs = g_csrc + beg;
        float s = -3.4e38f;
        int p = 0;
        int p4 = d & ~3;
        for (; p < p4; p += 4) {
            int i0 = cs[p + 0];
            int i1 = cs[p + 1];
            int i2 = cs[p + 2];
            int i3 = cs[p + 3];
            float v0 = g_ab[(size_t)i0 * 256 + l];
            float v1 = g_ab[(size_t)i1 * 256 + l];
            float v2 = g_ab[(size_t)i2 * 256 + l];
            float v3 = g_ab[(size_t)i3 * 256 + l];
            s = fmaxf(s, fmaxf(fmaxf(v0, v1), fmaxf(v2, v3)));
        }
        for (; p < d; p++) s = fmaxf(s, g_ab[(size_t)cs[p] * 256 + l]);
        out = fmaxf(s + g_ab[(size_t)n * 256 + 128 + l] + bmsg[l], 0.f);
    }
    g_agg[(size_t)n * 128 + l] = out;
}

// ---------------- decoder dots + mx reset ----------------
__global__ void uv_kernel(const float* __restrict__ Wdec) {
    int gt = blockIdx.x * blockDim.x + threadIdx.x;
    int w = gt >> 5, lane = gt & 31;
    if (w >= NN) return;
    float4 hv = ((const float4*)(g_h + (size_t)w * 128))[lane];
    float4 w1 = ((const float4*)Wdec)[lane];
    float4 w2 = ((const float4*)(Wdec + 128))[lane];
    float pu = hv.x * w1.x + hv.y * w1.y + hv.z * w1.z + hv.w * w1.w;
    float pv = hv.x * w2.x + hv.y * w2.y + hv.z * w2.z + hv.w * w2.w;
#pragma unroll
    for (int o = 16; o; o >>= 1) {
        pu += __shfl_down_sync(0xffffffffu, pu, o);
        pv += __shfl_down_sync(0xffffffffu, pv, o);
    }
    if (lane == 0) {
        g_u[w] = pu;
        g_v[w] = pv;
        g_mx[w] = 0;  // reset for this iteration's alpha pass
    }
}

// ---------------- edge alpha + incident-max ----------------
__global__ void alpha_kernel(const int* __restrict__ src, const int* __restrict__ dst,
                             const float* __restrict__ bdec, float* __restrict__ preds_out) {
    int e = blockIdx.x * blockDim.x + threadIdx.x;
    if (e >= EE) return;
    int sn = src[e], dn = dst[e];
    float x = g_u[sn] + g_v[dn] + bdec[0];
    float al = 1.f / (1.f + expf(-x));
    preds_out[e] = al;
    g_alpha[e] = al;
    int bits = __float_as_int(al);  // al >= 0, bit order == float order
    atomicMax(&g_mx[sn], bits);
    atomicMax(&g_mx[dn], bits);
}

// ---------------- parents: single packed atomicMax pass ----------------
__global__ void pack_kernel(const int* __restrict__ dst) {
    int e = blockIdx.x * blockDim.x + threadIdx.x;
    if (e >= EE) return;
    unsigned long long p =
        ((unsigned long long)(unsigned)__float_as_int(g_alpha[e]) << 32) |
        (unsigned)(EE - 1 - e);  // tie -> larger low bits -> smaller e (first occurrence)
    atomicMax(&g_pack[dst[e]], p);
}

__global__ void output_kernel(const int* __restrict__ src, float* __restrict__ out_reach,
                              float* __restrict__ out_par) {
    int n = blockIdx.x * blockDim.x + threadIdx.x;
    if (n >= NN) return;
    out_reach[n] = (__int_as_float(g_mx[n]) >= 0.4f) ? 1.f : 0.f;
    unsigned long long p = g_pack[n];
    if (p != 0ull) {
        int e = EE - 1 - (int)(p & 0xffffffffu);
        out_par[n] = (float)src[e];
    } else {
        out_par[n] = (float)n;
    }
}

// ---------------- launch ----------------
extern "C" void kernel_launch(void* const* d_in, const int* in_sizes, int n_in,
                              void* d_out, int out_size) {
    const float* pos  = (const float*)d_in[0];
    const float* s    = (const float*)d_in[1];
    const int*   ei   = (const int*)d_in[2];
    const float* Wenc = (const float*)d_in[3];
    const float* benc = (const float*)d_in[4];
    const float* W1   = (const float*)d_in[5];
    const float* W2   = (const float*)d_in[6];
    const float* bmsg = (const float*)d_in[7];
    const float* Wout = (const float*)d_in[8];
    const float* bout = (const float*)d_in[9];
    const float* Wdec = (const float*)d_in[10];
    const float* bdec = (const float*)d_in[11];
    const int* src = ei;
    const int* dst = ei + EE;
    float* out = (float*)d_out;

    const int TB = 256;
    const int MB = (NN + 127) / 128;  // 157
    init_kernel<<<(NN * LD + TB - 1) / TB, TB>>>(s);
    deg_kernel<<<(EE + TB - 1) / TB, TB>>>(dst);
    scan_kernel<<<1, 1024>>>();
    fill_kernel<<<(EE + TB - 1) / TB, TB>>>(src, dst);

    // precompute pre[r] = z_r @ [W1_top | W2_top]
    gemm_kernel<0><<<dim3(MB, 2, 2), 256>>>(W1, W2, pos, Wenc, benc, nullptr);

    for (int it = 0; it < MAXIT; it++) {
        // ab = h @ [W1_bot | W2_bot] + pre[reach]
        gemm_kernel<1><<<dim3(MB, 2), 256>>>(W1 + 128 * 128, W2 + 128 * 128,
                                             nullptr, nullptr, nullptr, nullptr);
        aggregate_kernel<<<(NN + 1) / 2, 256>>>(bmsg);
        gemm_kernel<2><<<dim3(MB, 1), 256>>>(Wout, nullptr, nullptr, nullptr, nullptr, bout);
        uv_kernel<<<(NN * 32 + TB - 1) / TB, TB>>>(Wdec);
        alpha_kernel<<<(EE + TB - 1) / TB, TB>>>(src, dst, bdec, out + (size_t)it * EE);
    }
    pack_kernel<<<(EE + TB - 1) / TB, TB>>>(dst);
    output_kernel<<<(NN + TB - 1) / TB, TB>>>(src, out + 10ull * EE, out + 10ull * EE + NN);
}

// round 13
// speedup vs baseline: 1.1859x; 1.1859x over previous
#include <cuda_runtime.h>
#include <math.h>

#define NN 20000
#define EE 320000
#define LD 128
#define MAXIT 10

// ---------------- device scratch ----------------
__device__ __align__(16) float g_h[NN * LD];          // hidden state
__device__ __align__(16) float g_ab[NN * 2 * LD];     // [a | b] per node
__device__ __align__(16) float g_agg[NN * LD];        // aggregated messages
__device__ __align__(16) float g_pre[2ull * NN * 2 * LD]; // z_r @ [W1_top|W2_top], r in {0,1}
__device__ __align__(16) float g_u[NN];
__device__ __align__(16) float g_v[NN];
__device__ __align__(16) float g_alpha[EE];
__device__ int g_mx[NN];                              // max alpha bits over incident edges
__device__ unsigned long long g_pack[NN];             // (alpha_bits<<32)|(EE-1-e) max
__device__ int g_deg[NN];
__device__ int g_off[NN];
__device__ int g_cursor[NN];
__device__ int g_csrc[EE];                            // CSR-by-dst source ids

// ---------------- init ----------------
__global__ void init_kernel(const float* __restrict__ s) {
    int idx = blockIdx.x * blockDim.x + threadIdx.x;
    if (idx < NN * LD) g_h[idx] = 0.f;
    if (idx < NN) {
        g_deg[idx] = 0;
        g_mx[idx] = (s[idx] > 0.f) ? 0x3f800000 : 0;  // reach(iter0) = s
        g_pack[idx] = 0ull;
    }
}

// ---------------- CSR build (by dst) ----------------
__global__ void deg_kernel(const int* __restrict__ dst) {
    int e = blockIdx.x * blockDim.x + threadIdx.x;
    if (e < EE) atomicAdd(&g_deg[dst[e]], 1);
}

__global__ void scan_kernel() {  // single block, 1024 threads
    __shared__ int part[1024];
    int t = threadIdx.x;
    const int chunk = (NN + 1023) / 1024;
    int b0 = t * chunk;
    int acc = 0;
    for (int i = 0; i < chunk; i++) {
        int idx = b0 + i;
        if (idx < NN) acc += g_deg[idx];
    }
    part[t] = acc;
    __syncthreads();
    for (int o = 1; o < 1024; o <<= 1) {
        int v = (t >= o) ? part[t - o] : 0;
        __syncthreads();
        part[t] += v;
        __syncthreads();
    }
    int run = (t == 0) ? 0 : part[t - 1];
    for (int i = 0; i < chunk; i++) {
        int idx = b0 + i;
        if (idx < NN) {
            g_off[idx] = run;
            g_cursor[idx] = run;
            run += g_deg[idx];
        }
    }
}

__global__ void fill_kernel(const int* __restrict__ src, const int* __restrict__ dst) {
    int e = blockIdx.x * blockDim.x + threadIdx.x;
    if (e < EE) {
        int p = atomicAdd(&g_cursor[dst[e]], 1);
        g_csrc[p] = src[e];
    }
}

// ---------------- unified scalar-FFMA GEMM (R6-proven: BM=128 BN=64 BK=16, 8x4) ----------------
// MODE 0: pre[r] = z_r(pos) @ [W1_top|W2_top]    grid (157,4,2)
// MODE 1: ab = h @ [W1_bot|W2_bot] + pre[reach]  grid (157,4)
// MODE 2: h = relu(agg @ Wout + bout)            grid (157,2)
template <int MODE>
__global__ __launch_bounds__(256) void gemm_kernel(
    const float* __restrict__ B1, const float* __restrict__ B2,
    const float* __restrict__ pos, const float* __restrict__ We,
    const float* __restrict__ be, const float* __restrict__ bias) {
    __shared__ float As[16][132];
    __shared__ float Bs[16][64];
    int m0 = blockIdx.x * 128;
    int j0 = blockIdx.y * 64;
    int r = (MODE == 0) ? (int)blockIdx.z : 0;
    const float* Bptr;
    int jb;
    if (MODE == 2) { Bptr = B1; jb = j0; }
    else if (j0 < 128) { Bptr = B1; jb = j0; }
    else { Bptr = B2; jb = j0 - 128; }
    int t = threadIdx.x, tx = t & 15, ty = t >> 4;
    float c[8][4] = {};

    for (int kt = 0; kt < 128; kt += 16) {
#pragma unroll
        for (int rr = 0; rr < 2; rr++) {
            int f = t + rr * 256;
            int mloc = f >> 2, k4 = (f & 3) * 4;
            int m = m0 + mloc;
            float4 av = make_float4(0.f, 0.f, 0.f, 0.f);
            if (m < NN) {
                if (MODE == 0) {
                    float p = pos[m];
                    float rf = (float)r;
                    float4 w0 = *(const float4*)(We + kt + k4);
                    float4 w1 = *(const float4*)(We + 128 + kt + k4);
                    float4 b0 = *(const float4*)(be + kt + k4);
                    av.x = fmaxf(fmaf(p, w0.x, fmaf(rf, w1.x, b0.x)), 0.f);
                    av.y = fmaxf(fmaf(p, w0.y, fmaf(rf, w1.y, b0.y)), 0.f);
                    av.z = fmaxf(fmaf(p, w0.z, fmaf(rf, w1.z, b0.z)), 0.f);
                    av.w = fmaxf(fmaf(p, w0.w, fmaf(rf, w1.w, b0.w)), 0.f);
                } else if (MODE == 1) {
                    av = *(const float4*)(g_h + (size_t)m * 128 + kt + k4);
                } else {
                    av = *(const float4*)(g_agg + (size_t)m * 128 + kt + k4);
                }
            }
            As[k4 + 0][mloc] = av.x;
            As[k4 + 1][mloc] = av.y;
            As[k4 + 2][mloc] = av.z;
            As[k4 + 3][mloc] = av.w;
        }
        {
            int kk = t >> 4, j4 = (t & 15) * 4;
            *(float4*)&Bs[kk][j4] = *(const float4*)(Bptr + (size_t)(kt + kk) * 128 + jb + j4);
        }
        __syncthreads();
#pragma unroll
        for (int k = 0; k < 16; k++) {
            float4 a0 = *(const float4*)&As[k][ty * 8];
            float4 a1 = *(const float4*)&As[k][ty * 8 + 4];
            float4 b = *(const float4*)&Bs[k][tx * 4];
            float ar[8] = {a0.x, a0.y, a0.z, a0.w, a1.x, a1.y, a1.z, a1.w};
            float br[4] = {b.x, b.y, b.z, b.w};
#pragma unroll
            for (int i = 0; i < 8; i++)
#pragma unroll
                for (int jj = 0; jj < 4; jj++) c[i][jj] = fmaf(ar[i], br[jj], c[i][jj]);
        }
        __syncthreads();
    }

#pragma unroll
    for (int i = 0; i < 8; i++) {
        int m = m0 + ty * 8 + i;
        if (m >= NN) continue;
        int jc = j0 + tx * 4;
        float4 v = make_float4(c[i][0], c[i][1], c[i][2], c[i][3]);
        if (MODE == 0) {
            *(float4*)(g_pre + ((size_t)r * NN + m) * 256 + jc) = v;
        } else if (MODE == 1) {
            int sel = (__int_as_float(g_mx[m]) >= 0.4f) ? 1 : 0;
            float4 pr = *(const float4*)(g_pre + ((size_t)sel * NN + m) * 256 + jc);
            v.x += pr.x; v.y += pr.y; v.z += pr.z; v.w += pr.w;
            *(float4*)(g_ab + (size_t)m * 256 + jc) = v;
        } else {
            float4 bb = *(const float4*)(bias + jc);
            v.x = fmaxf(v.x + bb.x, 0.f);
            v.y = fmaxf(v.y + bb.y, 0.f);
            v.z = fmaxf(v.z + bb.z, 0.f);
            v.w = fmaxf(v.w + bb.w, 0.f);
            *(float4*)(g_h + (size_t)m * 128 + jc) = v;
        }
    }
}

// ---------------- aggregate: agg[n] = relu(max_in a[src] + b[n] + bmsg) ----------------
// 1 node per 128-thread block, unroll-4 gather for MLP
__global__ __launch_bounds__(128) void aggregate_kernel(const float* __restrict__ bmsg) {
    int n = blockIdx.x;
    int l = threadIdx.x;
    int beg = g_off[n];
    int d = g_deg[n];
    float out = 0.f;
    if (d > 0) {
        const int* cs = g_csrc + beg;
        float s = -3.4e38f;
        int p = 0;
        int p4 = d & ~3;
        for (; p < p4; p += 4) {
            int i0 = cs[p + 0];
            int i1 = cs[p + 1];
            int i2 = cs[p + 2];
            int i3 = cs[p + 3];
            float v0 = g_ab[(size_t)i0 * 256 + l];
            float v1 = g_ab[(size_t)i1 * 256 + l];
            float v2 = g_ab[(size_t)i2 * 256 + l];
            float v3 = g_ab[(size_t)i3 * 256 + l];
            s = fmaxf(s, fmaxf(fmaxf(v0, v1), fmaxf(v2, v3)));
        }
        for (; p < d; p++) s = fmaxf(s, g_ab[(size_t)cs[p] * 256 + l]);
        out = fmaxf(s + g_ab[(size_t)n * 256 + 128 + l] + bmsg[l], 0.f);
    }
    g_agg[(size_t)n * 128 + l] = out;
}

// ---------------- decoder dots + mx reset ----------------
__global__ void uv_kernel(const float* __restrict__ Wdec) {
    int gt = blockIdx.x * blockDim.x + threadIdx.x;
    int w = gt >> 5, lane = gt & 31;
    if (w >= NN) return;
    float4 hv = ((const float4*)(g_h + (size_t)w * 128))[lane];
    float4 w1 = ((const float4*)Wdec)[lane];
    float4 w2 = ((const float4*)(Wdec + 128))[lane];
    float pu = hv.x * w1.x + hv.y * w1.y + hv.z * w1.z + hv.w * w1.w;
    float pv = hv.x * w2.x + hv.y * w2.y + hv.z * w2.z + hv.w * w2.w;
#pragma unroll
    for (int o = 16; o; o >>= 1) {
        pu += __shfl_down_sync(0xffffffffu, pu, o);
        pv += __shfl_down_sync(0xffffffffu, pv, o);
    }
    if (lane == 0) {
        g_u[w] = pu;
        g_v[w] = pv;
        g_mx[w] = 0;  // reset for this iteration's alpha pass
    }
}

// ---------------- edge alpha + incident-max ----------------
__global__ void alpha_kernel(const int* __restrict__ src, const int* __restrict__ dst,
                             const float* __restrict__ bdec, float* __restrict__ preds_out) {
    int e = blockIdx.x * blockDim.x + threadIdx.x;
    if (e >= EE) return;
    int sn = src[e], dn = dst[e];
    float x = g_u[sn] + g_v[dn] + bdec[0];
    float al = 1.f / (1.f + expf(-x));
    preds_out[e] = al;
    g_alpha[e] = al;
    int bits = __float_as_int(al);  // al >= 0, bit order == float order
    atomicMax(&g_mx[sn], bits);
    atomicMax(&g_mx[dn], bits);
}

// ---------------- parents: single packed atomicMax pass ----------------
__global__ void pack_kernel(const int* __restrict__ dst) {
    int e = blockIdx.x * blockDim.x + threadIdx.x;
    if (e >= EE) return;
    unsigned long long p =
        ((unsigned long long)(unsigned)__float_as_int(g_alpha[e]) << 32) |
        (unsigned)(EE - 1 - e);  // tie -> larger low bits -> smaller e (first occurrence)
    atomicMax(&g_pack[dst[e]], p);
}

__global__ void output_kernel(const int* __restrict__ src, float* __restrict__ out_reach,
                              float* __restrict__ out_par) {
    int n = blockIdx.x * blockDim.x + threadIdx.x;
    if (n >= NN) return;
    out_reach[n] = (__int_as_float(g_mx[n]) >= 0.4f) ? 1.f : 0.f;
    unsigned long long p = g_pack[n];
    if (p != 0ull) {
        int e = EE - 1 - (int)(p & 0xffffffffu);
        out_par[n] = (float)src[e];
    } else {
        out_par[n] = (float)n;
    }
}

// ---------------- launch ----------------
extern "C" void kernel_launch(void* const* d_in, const int* in_sizes, int n_in,
                              void* d_out, int out_size) {
    const float* pos  = (const float*)d_in[0];
    const float* s    = (const float*)d_in[1];
    const int*   ei   = (const int*)d_in[2];
    const float* Wenc = (const float*)d_in[3];
    const float* benc = (const float*)d_in[4];
    const float* W1   = (const float*)d_in[5];
    const float* W2   = (const float*)d_in[6];
    const float* bmsg = (const float*)d_in[7];
    const float* Wout = (const float*)d_in[8];
    const float* bout = (const float*)d_in[9];
    const float* Wdec = (const float*)d_in[10];
    const float* bdec = (const float*)d_in[11];
    const int* src = ei;
    const int* dst = ei + EE;
    float* out = (float*)d_out;

    const int TB = 256;
    const int MB = (NN + 127) / 128;  // 157
    init_kernel<<<(NN * LD + TB - 1) / TB, TB>>>(s);
    deg_kernel<<<(EE + TB - 1) / TB, TB>>>(dst);
    scan_kernel<<<1, 1024>>>();
    fill_kernel<<<(EE + TB - 1) / TB, TB>>>(src, dst);

    // precompute pre[r] = z_r @ [W1_top | W2_top]
    gemm_kernel<0><<<dim3(MB, 4, 2), 256>>>(W1, W2, pos, Wenc, benc, nullptr);

    for (int it = 0; it < MAXIT; it++) {
        // ab = h @ [W1_bot | W2_bot] + pre[reach]
        gemm_kernel<1><<<dim3(MB, 4), 256>>>(W1 + 128 * 128, W2 + 128 * 128,
                                             nullptr, nullptr, nullptr, nullptr);
        aggregate_kernel<<<NN, 128>>>(bmsg);
        gemm_kernel<2><<<dim3(MB, 2), 256>>>(Wout, nullptr, nullptr, nullptr, nullptr, bout);
        uv_kernel<<<(NN * 32 + TB - 1) / TB, TB>>>(Wdec);
        alpha_kernel<<<(EE + TB - 1) / TB, TB>>>(src, dst, bdec, out + (size_t)it * EE);
    }
    pack_kernel<<<(EE + TB - 1) / TB, TB>>>(dst);
    output_kernel<<<(NN + TB - 1) / TB, TB>>>(src, out + 10ull * EE, out + 10ull * EE + NN);
}